// round 7
// baseline (speedup 1.0000x reference)
#include <cuda_runtime.h>
#include <cuda_fp16.h>
#include <math.h>
#include <stdint.h>

#define NR 131072
#define EPS_N 1e-3f
#define LN_EPS 1e-5f

// ---- global scratch (allocation-free) ----
__device__ __half g_wd[128 * 512];
__device__ __half g_wl[512 * 512];
__device__ __half g_v2[(size_t)NR * 512];

// ---- helpers ----
__device__ __forceinline__ uint32_t smem_u32(const void* p) {
    uint32_t a;
    asm("{ .reg .u64 t; cvta.to.shared.u64 t, %1; cvt.u32.u64 %0, t; }" : "=r"(a) : "l"(p));
    return a;
}
__device__ __forceinline__ void mma_f16(float* c, uint32_t a0, uint32_t a1, uint32_t a2, uint32_t a3,
                                        uint32_t b0, uint32_t b1) {
    asm volatile("mma.sync.aligned.m16n8k16.row.col.f32.f16.f16.f32 "
                 "{%0,%1,%2,%3},{%4,%5,%6,%7},{%8,%9},{%0,%1,%2,%3};"
                 : "+f"(c[0]), "+f"(c[1]), "+f"(c[2]), "+f"(c[3])
                 : "r"(a0), "r"(a1), "r"(a2), "r"(a3), "r"(b0), "r"(b1));
}
#define LDSM4(R, A) \
    asm volatile("ldmatrix.sync.aligned.m8n8.x4.shared.b16 {%0,%1,%2,%3},[%4];" \
                 : "=r"((R)[0]), "=r"((R)[1]), "=r"((R)[2]), "=r"((R)[3]) : "r"(A))
#define CP16(dst, src) asm volatile("cp.async.ca.shared.global [%0],[%1],16;" :: "r"(dst), "l"(src) : "memory")
#define CPCOMMIT()     asm volatile("cp.async.commit_group;" ::: "memory")
#define CPWAIT0()      asm volatile("cp.async.wait_group 0;" ::: "memory")

// ---------------- prep: convert weights to fp16 ----------------
__global__ void __launch_bounds__(256) kprep(const float* __restrict__ Wd,
                                             const float* __restrict__ Wl) {
    int i = blockIdx.x * 256 + threadIdx.x;
    if (i < 128 * 512) g_wd[i] = __float2half_rn(Wd[i]);
    if (i < 512 * 512) g_wl[i] = __float2half_rn(Wl[i]);
}

// ---------------- Kernel 1: HMMA GEMM1 + scalarizer epilogue ----------------
// CTA: 64 v-rows = 192 A-rows, N=128, K chunks of 32, double-buffered.
// 512 threads, warp grid 4(M)x4(N): warp tile 48x32. Single-pass fp16.
#define K1_A(b) (1536 + (b) * 15360)
#define K1_B(b) (32256 + (b) * 10240)
#define VST 132
#define K1_SMEM 102912

__global__ void __launch_bounds__(512) k1_kernel(const float* __restrict__ v,
                                                 const float* __restrict__ We) {
    extern __shared__ char smem[];
    const uint32_t sb = smem_u32(smem);
    const int tid = threadIdx.x, wid = tid >> 5, lane = tid & 31;
    const int wm = wid & 3, wn = wid >> 2;
    const int fr = lane >> 2, fc = lane & 3;
    const int lr = lane & 7, b8 = (lane >> 3) & 1, b16 = (lane >> 4) & 1;
    const int blk = blockIdx.x;
    const float* vbase = v + (size_t)blk * 192 * 512;

    float* sWe = (float*)smem;
    for (int i = tid; i < 384; i += 512) sWe[i] = We[i];

    const int brow = tid >> 2, bseg = tid & 3;
    const uint32_t bdst = (uint32_t)(brow * 80 + bseg * 16);
    const __half* bsrc = g_wd + brow * 512 + bseg * 8;

    const uint32_t aoff = (uint32_t)((wm * 48 + lr + b8 * 8) * 80 + b16 * 16);
    const uint32_t boff = (uint32_t)((wn * 32 + lr + b8 * 8) * 80 + b16 * 16);

    float acc[3][4][4];
#pragma unroll
    for (int m = 0; m < 3; m++)
#pragma unroll
        for (int n = 0; n < 4; n++)
#pragma unroll
            for (int j = 0; j < 4; j++) acc[m][n][j] = 0.f;

    float4 va[3];
    // prologue: chunk 0
    CP16(sb + K1_B(0) + bdst, bsrc);
    CPCOMMIT();
#pragma unroll
    for (int t = 0; t < 3; t++) {
        int lin = tid + 512 * t;
        int g = lin >> 3, q = lin & 7;
        va[t] = *(const float4*)(vbase + (size_t)g * 512 + q * 4);
    }
#pragma unroll
    for (int t = 0; t < 3; t++) {
        int lin = tid + 512 * t;
        int g = lin >> 3, q = lin & 7;
        __half2 p0 = __floats2half2_rn(va[t].x, va[t].y);
        __half2 p1 = __floats2half2_rn(va[t].z, va[t].w);
        *(uint2*)(smem + K1_A(0) + g * 80 + q * 8) =
            make_uint2(*(uint32_t*)&p0, *(uint32_t*)&p1);
    }
    CPWAIT0();
    __syncthreads();

    int cur = 0;
    for (int c = 0; c < 16; c++) {
        if (c < 15) {
            const int k0n = (c + 1) * 32;
            CP16(sb + K1_B(cur ^ 1) + bdst, bsrc + k0n);
            CPCOMMIT();
#pragma unroll
            for (int t = 0; t < 3; t++) {
                int lin = tid + 512 * t;
                int g = lin >> 3, q = lin & 7;
                va[t] = *(const float4*)(vbase + (size_t)g * 512 + k0n + q * 4);
            }
        }
        const uint32_t A = sb + K1_A(cur), B = sb + K1_B(cur);
#pragma unroll
        for (int ks = 0; ks < 2; ks++) {
            uint32_t a[3][4], b[2][4];
#pragma unroll
            for (int m = 0; m < 3; m++) LDSM4(a[m], A + aoff + m * 1280 + ks * 32);
#pragma unroll
            for (int p = 0; p < 2; p++) LDSM4(b[p], B + boff + p * 1280 + ks * 32);
#pragma unroll
            for (int m = 0; m < 3; m++)
#pragma unroll
                for (int n = 0; n < 4; n++)
                    mma_f16(acc[m][n], a[m][0], a[m][1], a[m][2], a[m][3],
                            b[n >> 1][n & 1], b[n >> 1][2 + (n & 1)]);
        }
        if (c < 15) {
#pragma unroll
            for (int t = 0; t < 3; t++) {
                int lin = tid + 512 * t;
                int g = lin >> 3, q = lin & 7;
                __half2 p0 = __floats2half2_rn(va[t].x, va[t].y);
                __half2 p1 = __floats2half2_rn(va[t].z, va[t].w);
                *(uint2*)(smem + K1_A(cur ^ 1) + g * 80 + q * 8) =
                    make_uint2(*(uint32_t*)&p0, *(uint32_t*)&p1);
            }
            CPWAIT0();
        }
        __syncthreads();
        cur ^= 1;
    }

    // dump acc -> vred
    float* vred = (float*)(smem + 1536);
#pragma unroll
    for (int m = 0; m < 3; m++) {
        int row = wm * 48 + m * 16 + fr;
#pragma unroll
        for (int n = 0; n < 4; n++) {
            int col = wn * 32 + n * 8 + fc * 2;
            *(float2*)(vred + row * VST + col) = make_float2(acc[m][n][0], acc[m][n][1]);
            *(float2*)(vred + (row + 8) * VST + col) = make_float2(acc[m][n][2], acc[m][n][3]);
        }
    }
    __syncthreads();

    // ---- epilogue: norms, directions, projections -> v2 (fp16) ----
    float we[3][4];
#pragma unroll
    for (int e = 0; e < 3; e++)
#pragma unroll
        for (int c = 0; c < 4; c++) we[e][c] = sWe[e * 128 + lane + 32 * c];

    for (int t = 0; t < 4; t++) {
        int r = wid + 16 * t;
        size_t gr = (size_t)blk * 64 + r;
        float vr[3][4];
#pragma unroll
        for (int i = 0; i < 3; i++)
#pragma unroll
            for (int c = 0; c < 4; c++)
                vr[i][c] = vred[(r * 3 + i) * VST + lane + 32 * c];

        float d9[3][3];
#pragma unroll
        for (int i = 0; i < 3; i++)
#pragma unroll
            for (int e = 0; e < 3; e++) {
                float s = 0.f;
#pragma unroll
                for (int c = 0; c < 4; c++) s = fmaf(vr[i][c], we[e][c], s);
#pragma unroll
                for (int o = 16; o > 0; o >>= 1) s += __shfl_xor_sync(0xffffffffu, s, o);
                d9[i][e] = s;
            }
        float nd[3][3];
#pragma unroll
        for (int e = 0; e < 3; e++) {
            float dn = sqrtf(d9[0][e] * d9[0][e] + d9[1][e] * d9[1][e] + d9[2][e] * d9[2][e]);
            float inv = 1.f / (dn + EPS_N);
            nd[0][e] = d9[0][e] * inv;
            nd[1][e] = d9[1][e] * inv;
            nd[2][e] = d9[2][e] * inv;
        }
        __half* ov = g_v2 + gr * 512;
#pragma unroll
        for (int c = 0; c < 4; c++) {
            float n = sqrtf(vr[0][c] * vr[0][c] + vr[1][c] * vr[1][c] + vr[2][c] * vr[2][c]);
            float invn = 1.f / (n + EPS_N);
            int k = lane + 32 * c;
            ov[k] = __float2half_rn(n);
#pragma unroll
            for (int e = 0; e < 3; e++) {
                float p = (vr[0][c] * nd[0][e] + vr[1][c] * nd[1][e] + vr[2][c] * nd[2][e]) * invn;
                ov[128 + e * 128 + k] = __float2half_rn(p);
            }
        }
    }
}

// ---------------- Kernel 2: HMMA GEMM2 fused with LayerNorm+GELU ----------------
// CTA: 64 rows x full 512 cols. 512 threads, warp grid 2(M)x8(N): tile 32x64.
#define K2_A(b) ((b) * 5120)
#define K2_B(b) (10240 + (b) * 40960)
#define K2_PSUM 92160
#define K2_PSQ 94208
#define K2_SMEM 96256

__global__ void __launch_bounds__(512, 2) k2_kernel(const float* __restrict__ bias,
                                                    const float* __restrict__ gamma,
                                                    const float* __restrict__ beta,
                                                    float* __restrict__ out) {
    extern __shared__ char smem[];
    const uint32_t sb = smem_u32(smem);
    const int tid = threadIdx.x, wid = tid >> 5, lane = tid & 31;
    const int wm = wid & 1, wn = wid >> 1;
    const int fr = lane >> 2, fc = lane & 3;
    const int lr = lane & 7, b8 = (lane >> 3) & 1, b16 = (lane >> 4) & 1;
    const size_t row0 = (size_t)blockIdx.x * 64;

    const int arow = (tid >> 2) & 63, aseg = tid & 3;
    const __half* asrc = g_v2 + (row0 + arow) * 512 + aseg * 8;
    const uint32_t adst = (uint32_t)(arow * 80 + aseg * 16);

    const uint32_t aoff = (uint32_t)((wm * 32 + lr + b8 * 8) * 80 + b16 * 16);
    const uint32_t boff = (uint32_t)((wn * 64 + lr + b8 * 8) * 80 + b16 * 16);

    float acc[2][8][4];
#pragma unroll
    for (int m = 0; m < 2; m++)
#pragma unroll
        for (int n = 0; n < 8; n++)
#pragma unroll
            for (int j = 0; j < 4; j++) acc[m][n][j] = 0.f;

    // prologue: chunk 0
    {
        if (tid < 256) CP16(sb + K2_A(0) + adst, asrc);
#pragma unroll
        for (int i = 0; i < 4; i++) {
            int lin = tid + 512 * i;
            int r = lin >> 2, seg = lin & 3;
            CP16(sb + K2_B(0) + (uint32_t)(r * 80 + seg * 16), g_wl + (size_t)r * 512 + seg * 8);
        }
        CPCOMMIT();
        CPWAIT0();
        __syncthreads();
    }
    int cur = 0;
    for (int c = 0; c < 16; c++) {
        if (c < 15) {
            const int k0n = (c + 1) * 32;
            if (tid < 256) CP16(sb + K2_A(cur ^ 1) + adst, asrc + k0n);
#pragma unroll
            for (int i = 0; i < 4; i++) {
                int lin = tid + 512 * i;
                int r = lin >> 2, seg = lin & 3;
                CP16(sb + K2_B(cur ^ 1) + (uint32_t)(r * 80 + seg * 16),
                     g_wl + (size_t)r * 512 + k0n + seg * 8);
            }
            CPCOMMIT();
        }
        const uint32_t A = sb + K2_A(cur), B = sb + K2_B(cur);
#pragma unroll
        for (int ks = 0; ks < 2; ks++) {
            uint32_t a[2][4], b[4][4];
#pragma unroll
            for (int m = 0; m < 2; m++) LDSM4(a[m], A + aoff + m * 1280 + ks * 32);
#pragma unroll
            for (int p = 0; p < 4; p++) LDSM4(b[p], B + boff + p * 1280 + ks * 32);
#pragma unroll
            for (int m = 0; m < 2; m++)
#pragma unroll
                for (int n = 0; n < 8; n++)
                    mma_f16(acc[m][n], a[m][0], a[m][1], a[m][2], a[m][3],
                            b[n >> 1][n & 1], b[n >> 1][2 + (n & 1)]);
        }
        if (c < 15) CPWAIT0();
        __syncthreads();
        cur ^= 1;
    }

    // ---- fused epilogue: bias + LayerNorm + exact GELU ----
#pragma unroll
    for (int n = 0; n < 8; n++) {
        int col = wn * 64 + n * 8 + fc * 2;
        float2 bb = *(const float2*)(bias + col);
#pragma unroll
        for (int m = 0; m < 2; m++) {
            acc[m][n][0] += bb.x; acc[m][n][1] += bb.y;
            acc[m][n][2] += bb.x; acc[m][n][3] += bb.y;
        }
    }
    float* psum = (float*)(smem + K2_PSUM);
    float* psq  = (float*)(smem + K2_PSQ);
#pragma unroll
    for (int m = 0; m < 2; m++)
#pragma unroll
        for (int h = 0; h < 2; h++) {
            float s = 0.f, q = 0.f;
#pragma unroll
            for (int n = 0; n < 8; n++) {
                float e0 = acc[m][n][h * 2], e1 = acc[m][n][h * 2 + 1];
                s += e0 + e1;
                q += e0 * e0 + e1 * e1;
            }
            s += __shfl_xor_sync(0xffffffffu, s, 1);
            s += __shfl_xor_sync(0xffffffffu, s, 2);
            q += __shfl_xor_sync(0xffffffffu, q, 1);
            q += __shfl_xor_sync(0xffffffffu, q, 2);
            int rr = wm * 32 + m * 16 + h * 8 + fr;
            if (fc == 0) { psum[wn * 64 + rr] = s; psq[wn * 64 + rr] = q; }
        }
    __syncthreads();

    float gg[8][2], bb2[8][2];
#pragma unroll
    for (int n = 0; n < 8; n++) {
        int col = wn * 64 + n * 8 + fc * 2;
        float2 g2 = *(const float2*)(gamma + col);
        float2 b2 = *(const float2*)(beta + col);
        gg[n][0] = g2.x; gg[n][1] = g2.y;
        bb2[n][0] = b2.x; bb2[n][1] = b2.y;
    }
    const float invs2 = 0.70710678118654752f;
#pragma unroll
    for (int m = 0; m < 2; m++)
#pragma unroll
        for (int h = 0; h < 2; h++) {
            int rr = wm * 32 + m * 16 + h * 8 + fr;
            float S = 0.f, Q = 0.f;
#pragma unroll
            for (int w = 0; w < 8; w++) { S += psum[w * 64 + rr]; Q += psq[w * 64 + rr]; }
            float mu = S * (1.f / 512.f);
            float var = Q * (1.f / 512.f) - mu * mu;
            float rstd = rsqrtf(var + LN_EPS);
            size_t orow = (row0 + rr) * 512;
#pragma unroll
            for (int n = 0; n < 8; n++) {
                int col = wn * 64 + n * 8 + fc * 2;
                float y0 = (acc[m][n][h * 2] - mu) * rstd * gg[n][0] + bb2[n][0];
                float y1 = (acc[m][n][h * 2 + 1] - mu) * rstd * gg[n][1] + bb2[n][1];
                float o0 = y0 * 0.5f * (1.f + erff(y0 * invs2));
                float o1 = y1 * 0.5f * (1.f + erff(y1 * invs2));
                *(float2*)(out + orow + col) = make_float2(o0, o1);
            }
        }
}

// ---------------- launch ----------------
extern "C" void kernel_launch(void* const* d_in, const int* in_sizes, int n_in,
                              void* d_out, int out_size) {
    const float* v     = (const float*)d_in[0];
    const float* Wd    = (const float*)d_in[1];
    const float* We    = (const float*)d_in[2];
    const float* Wl    = (const float*)d_in[3];
    const float* bl    = (const float*)d_in[4];
    const float* gamma = (const float*)d_in[5];
    const float* beta  = (const float*)d_in[6];
    float* out = (float*)d_out;

    cudaFuncSetAttribute(k1_kernel, cudaFuncAttributeMaxDynamicSharedMemorySize, K1_SMEM);
    cudaFuncSetAttribute(k2_kernel, cudaFuncAttributeMaxDynamicSharedMemorySize, K2_SMEM);

    kprep<<<1024, 256>>>(Wd, Wl);
    k1_kernel<<<NR / 64, 512, K1_SMEM>>>(v, We);
    k2_kernel<<<NR / 64, 512, K2_SMEM>>>(bl, gamma, beta, out);
}

// round 8
// speedup vs baseline: 1.9059x; 1.9059x over previous
#include <cuda_runtime.h>
#include <cuda_fp16.h>
#include <math.h>
#include <stdint.h>

#define NR 131072
#define EPS_N 1e-3f
#define LN_EPS 1e-5f

// ---- global scratch (allocation-free) ----
__device__ __half g_wd[128 * 512];
__device__ __half g_wl[512 * 512];
__device__ __half g_v2[(size_t)NR * 512];

// ---- helpers ----
__device__ __forceinline__ uint32_t smem_u32(const void* p) {
    uint32_t a;
    asm("{ .reg .u64 t; cvta.to.shared.u64 t, %1; cvt.u32.u64 %0, t; }" : "=r"(a) : "l"(p));
    return a;
}
__device__ __forceinline__ void mma_f16(float* c, uint32_t a0, uint32_t a1, uint32_t a2, uint32_t a3,
                                        uint32_t b0, uint32_t b1) {
    asm volatile("mma.sync.aligned.m16n8k16.row.col.f32.f16.f16.f32 "
                 "{%0,%1,%2,%3},{%4,%5,%6,%7},{%8,%9},{%0,%1,%2,%3};"
                 : "+f"(c[0]), "+f"(c[1]), "+f"(c[2]), "+f"(c[3])
                 : "r"(a0), "r"(a1), "r"(a2), "r"(a3), "r"(b0), "r"(b1));
}
#define LDSM4(R, A) \
    asm volatile("ldmatrix.sync.aligned.m8n8.x4.shared.b16 {%0,%1,%2,%3},[%4];" \
                 : "=r"((R)[0]), "=r"((R)[1]), "=r"((R)[2]), "=r"((R)[3]) : "r"(A))
#define CP16(dst, src) asm volatile("cp.async.ca.shared.global [%0],[%1],16;" :: "r"(dst), "l"(src) : "memory")
#define CPCOMMIT()     asm volatile("cp.async.commit_group;" ::: "memory")
#define CPWAIT0()      asm volatile("cp.async.wait_group 0;" ::: "memory")

// ---------------- prep: convert weights to fp16 ----------------
__global__ void __launch_bounds__(256) kprep(const float* __restrict__ Wd,
                                             const float* __restrict__ Wl) {
    int i = blockIdx.x * 256 + threadIdx.x;
    if (i < 128 * 512) g_wd[i] = __float2half_rn(Wd[i]);
    if (i < 512 * 512) g_wl[i] = __float2half_rn(Wl[i]);
}

// ---------------- Kernel 1: HMMA GEMM1 + scalarizer epilogue ----------------
// CTA: 64 v-rows = 192 A-rows, N=128, K chunks of 32, double-buffered.
// 512 threads, warp grid 4(M)x4(N): warp tile 48x32. Single-pass fp16.
#define K1_A(b) (1536 + (b) * 15360)
#define K1_B(b) (32256 + (b) * 10240)
#define VST 132
#define K1_SMEM 102912

__global__ void __launch_bounds__(512) k1_kernel(const float* __restrict__ v,
                                                 const float* __restrict__ We) {
    extern __shared__ char smem[];
    const uint32_t sb = smem_u32(smem);
    const int tid = threadIdx.x, wid = tid >> 5, lane = tid & 31;
    const int wm = wid & 3, wn = wid >> 2;
    const int fr = lane >> 2, fc = lane & 3;
    const int lr = lane & 7, b8 = (lane >> 3) & 1, b16 = (lane >> 4) & 1;
    const int blk = blockIdx.x;
    const float* vbase = v + (size_t)blk * 192 * 512;

    float* sWe = (float*)smem;
    for (int i = tid; i < 384; i += 512) sWe[i] = We[i];

    const int brow = tid >> 2, bseg = tid & 3;
    const uint32_t bdst = (uint32_t)(brow * 80 + bseg * 16);
    const __half* bsrc = g_wd + brow * 512 + bseg * 8;

    const uint32_t aoff = (uint32_t)((wm * 48 + lr + b8 * 8) * 80 + b16 * 16);
    const uint32_t boff = (uint32_t)((wn * 32 + lr + b8 * 8) * 80 + b16 * 16);

    float acc[3][4][4];
#pragma unroll
    for (int m = 0; m < 3; m++)
#pragma unroll
        for (int n = 0; n < 4; n++)
#pragma unroll
            for (int j = 0; j < 4; j++) acc[m][n][j] = 0.f;

    float4 va[3];
    // prologue: chunk 0
    CP16(sb + K1_B(0) + bdst, bsrc);
    CPCOMMIT();
#pragma unroll
    for (int t = 0; t < 3; t++) {
        int lin = tid + 512 * t;
        int g = lin >> 3, q = lin & 7;
        va[t] = *(const float4*)(vbase + (size_t)g * 512 + q * 4);
    }
#pragma unroll
    for (int t = 0; t < 3; t++) {
        int lin = tid + 512 * t;
        int g = lin >> 3, q = lin & 7;
        __half2 p0 = __floats2half2_rn(va[t].x, va[t].y);
        __half2 p1 = __floats2half2_rn(va[t].z, va[t].w);
        *(uint2*)(smem + K1_A(0) + g * 80 + q * 8) =
            make_uint2(*(uint32_t*)&p0, *(uint32_t*)&p1);
    }
    CPWAIT0();
    __syncthreads();

    int cur = 0;
    for (int c = 0; c < 16; c++) {
        if (c < 15) {
            const int k0n = (c + 1) * 32;
            CP16(sb + K1_B(cur ^ 1) + bdst, bsrc + k0n);
            CPCOMMIT();
#pragma unroll
            for (int t = 0; t < 3; t++) {
                int lin = tid + 512 * t;
                int g = lin >> 3, q = lin & 7;
                va[t] = *(const float4*)(vbase + (size_t)g * 512 + k0n + q * 4);
            }
        }
        const uint32_t A = sb + K1_A(cur), B = sb + K1_B(cur);
#pragma unroll
        for (int ks = 0; ks < 2; ks++) {
            uint32_t a[3][4], b[2][4];
#pragma unroll
            for (int m = 0; m < 3; m++) LDSM4(a[m], A + aoff + m * 1280 + ks * 32);
#pragma unroll
            for (int p = 0; p < 2; p++) LDSM4(b[p], B + boff + p * 1280 + ks * 32);
#pragma unroll
            for (int m = 0; m < 3; m++)
#pragma unroll
                for (int n = 0; n < 4; n++)
                    mma_f16(acc[m][n], a[m][0], a[m][1], a[m][2], a[m][3],
                            b[n >> 1][n & 1], b[n >> 1][2 + (n & 1)]);
        }
        if (c < 15) {
#pragma unroll
            for (int t = 0; t < 3; t++) {
                int lin = tid + 512 * t;
                int g = lin >> 3, q = lin & 7;
                __half2 p0 = __floats2half2_rn(va[t].x, va[t].y);
                __half2 p1 = __floats2half2_rn(va[t].z, va[t].w);
                *(uint2*)(smem + K1_A(cur ^ 1) + g * 80 + q * 8) =
                    make_uint2(*(uint32_t*)&p0, *(uint32_t*)&p1);
            }
            CPWAIT0();
        }
        __syncthreads();
        cur ^= 1;
    }

    // dump acc -> vred
    float* vred = (float*)(smem + 1536);
#pragma unroll
    for (int m = 0; m < 3; m++) {
        int row = wm * 48 + m * 16 + fr;
#pragma unroll
        for (int n = 0; n < 4; n++) {
            int col = wn * 32 + n * 8 + fc * 2;
            *(float2*)(vred + row * VST + col) = make_float2(acc[m][n][0], acc[m][n][1]);
            *(float2*)(vred + (row + 8) * VST + col) = make_float2(acc[m][n][2], acc[m][n][3]);
        }
    }
    __syncthreads();

    // ---- epilogue: norms, directions, projections -> v2 (fp16) ----
    float we[3][4];
#pragma unroll
    for (int e = 0; e < 3; e++)
#pragma unroll
        for (int c = 0; c < 4; c++) we[e][c] = sWe[e * 128 + lane + 32 * c];

    for (int t = 0; t < 4; t++) {
        int r = wid + 16 * t;
        size_t gr = (size_t)blk * 64 + r;
        float vr[3][4];
#pragma unroll
        for (int i = 0; i < 3; i++)
#pragma unroll
            for (int c = 0; c < 4; c++)
                vr[i][c] = vred[(r * 3 + i) * VST + lane + 32 * c];

        float d9[3][3];
#pragma unroll
        for (int i = 0; i < 3; i++)
#pragma unroll
            for (int e = 0; e < 3; e++) {
                float s = 0.f;
#pragma unroll
                for (int c = 0; c < 4; c++) s = fmaf(vr[i][c], we[e][c], s);
#pragma unroll
                for (int o = 16; o > 0; o >>= 1) s += __shfl_xor_sync(0xffffffffu, s, o);
                d9[i][e] = s;
            }
        float nd[3][3];
#pragma unroll
        for (int e = 0; e < 3; e++) {
            float dn = sqrtf(d9[0][e] * d9[0][e] + d9[1][e] * d9[1][e] + d9[2][e] * d9[2][e]);
            float inv = 1.f / (dn + EPS_N);
            nd[0][e] = d9[0][e] * inv;
            nd[1][e] = d9[1][e] * inv;
            nd[2][e] = d9[2][e] * inv;
        }
        __half* ov = g_v2 + gr * 512;
#pragma unroll
        for (int c = 0; c < 4; c++) {
            float n = sqrtf(vr[0][c] * vr[0][c] + vr[1][c] * vr[1][c] + vr[2][c] * vr[2][c]);
            float invn = 1.f / (n + EPS_N);
            int k = lane + 32 * c;
            ov[k] = __float2half_rn(n);
#pragma unroll
            for (int e = 0; e < 3; e++) {
                float p = (vr[0][c] * nd[0][e] + vr[1][c] * nd[1][e] + vr[2][c] * nd[2][e]) * invn;
                ov[128 + e * 128 + k] = __float2half_rn(p);
            }
        }
    }
}

// ---------------- Kernel 2: HMMA GEMM2 fused with LayerNorm+GELU ----------------
// CTA: 64 rows x full 512 cols. 512 threads, warp grid 2(M)x8(N): tile 32x64.
#define K2_A(b) ((b) * 5120)
#define K2_B(b) (10240 + (b) * 40960)
#define K2_PSUM 92160
#define K2_PSQ 94208
#define K2_SMEM 96256

__global__ void __launch_bounds__(512) k2_kernel(const float* __restrict__ bias,
                                                 const float* __restrict__ gamma,
                                                 const float* __restrict__ beta,
                                                 float* __restrict__ out) {
    extern __shared__ char smem[];
    const uint32_t sb = smem_u32(smem);
    const int tid = threadIdx.x, wid = tid >> 5, lane = tid & 31;
    const int wm = wid & 1, wn = wid >> 1;
    const int fr = lane >> 2, fc = lane & 3;
    const int lr = lane & 7, b8 = (lane >> 3) & 1, b16 = (lane >> 4) & 1;
    const size_t row0 = (size_t)blockIdx.x * 64;

    const int arow = (tid >> 2) & 63, aseg = tid & 3;
    const __half* asrc = g_v2 + (row0 + arow) * 512 + aseg * 8;
    const uint32_t adst = (uint32_t)(arow * 80 + aseg * 16);

    const uint32_t aoff = (uint32_t)((wm * 32 + lr + b8 * 8) * 80 + b16 * 16);
    const uint32_t boff = (uint32_t)((wn * 64 + lr + b8 * 8) * 80 + b16 * 16);

    float acc[2][8][4];
#pragma unroll
    for (int m = 0; m < 2; m++)
#pragma unroll
        for (int n = 0; n < 8; n++)
#pragma unroll
            for (int j = 0; j < 4; j++) acc[m][n][j] = 0.f;

    // prologue: chunk 0
    {
        if (tid < 256) CP16(sb + K2_A(0) + adst, asrc);
#pragma unroll
        for (int i = 0; i < 4; i++) {
            int lin = tid + 512 * i;
            int r = lin >> 2, seg = lin & 3;
            CP16(sb + K2_B(0) + (uint32_t)(r * 80 + seg * 16), g_wl + (size_t)r * 512 + seg * 8);
        }
        CPCOMMIT();
        CPWAIT0();
        __syncthreads();
    }
    int cur = 0;
    for (int c = 0; c < 16; c++) {
        if (c < 15) {
            const int k0n = (c + 1) * 32;
            if (tid < 256) CP16(sb + K2_A(cur ^ 1) + adst, asrc + k0n);
#pragma unroll
            for (int i = 0; i < 4; i++) {
                int lin = tid + 512 * i;
                int r = lin >> 2, seg = lin & 3;
                CP16(sb + K2_B(cur ^ 1) + (uint32_t)(r * 80 + seg * 16),
                     g_wl + (size_t)r * 512 + k0n + seg * 8);
            }
            CPCOMMIT();
        }
        const uint32_t A = sb + K2_A(cur), B = sb + K2_B(cur);
#pragma unroll
        for (int ks = 0; ks < 2; ks++) {
            uint32_t a[2][4], b[4][4];
#pragma unroll
            for (int m = 0; m < 2; m++) LDSM4(a[m], A + aoff + m * 1280 + ks * 32);
#pragma unroll
            for (int p = 0; p < 4; p++) LDSM4(b[p], B + boff + p * 1280 + ks * 32);
#pragma unroll
            for (int m = 0; m < 2; m++)
#pragma unroll
                for (int n = 0; n < 8; n++)
                    mma_f16(acc[m][n], a[m][0], a[m][1], a[m][2], a[m][3],
                            b[n >> 1][n & 1], b[n >> 1][2 + (n & 1)]);
        }
        if (c < 15) CPWAIT0();
        __syncthreads();
        cur ^= 1;
    }

    // ---- fused epilogue: bias + LayerNorm + exact GELU ----
#pragma unroll
    for (int n = 0; n < 8; n++) {
        int col = wn * 64 + n * 8 + fc * 2;
        float2 bb = *(const float2*)(bias + col);
#pragma unroll
        for (int m = 0; m < 2; m++) {
            acc[m][n][0] += bb.x; acc[m][n][1] += bb.y;
            acc[m][n][2] += bb.x; acc[m][n][3] += bb.y;
        }
    }
    float* psum = (float*)(smem + K2_PSUM);
    float* psq  = (float*)(smem + K2_PSQ);
#pragma unroll
    for (int m = 0; m < 2; m++)
#pragma unroll
        for (int h = 0; h < 2; h++) {
            float s = 0.f, q = 0.f;
#pragma unroll
            for (int n = 0; n < 8; n++) {
                float e0 = acc[m][n][h * 2], e1 = acc[m][n][h * 2 + 1];
                s += e0 + e1;
                q += e0 * e0 + e1 * e1;
            }
            s += __shfl_xor_sync(0xffffffffu, s, 1);
            s += __shfl_xor_sync(0xffffffffu, s, 2);
            q += __shfl_xor_sync(0xffffffffu, q, 1);
            q += __shfl_xor_sync(0xffffffffu, q, 2);
            int rr = wm * 32 + m * 16 + h * 8 + fr;
            if (fc == 0) { psum[wn * 64 + rr] = s; psq[wn * 64 + rr] = q; }
        }
    __syncthreads();

    float gg[8][2], bb2[8][2];
#pragma unroll
    for (int n = 0; n < 8; n++) {
        int col = wn * 64 + n * 8 + fc * 2;
        float2 g2 = *(const float2*)(gamma + col);
        float2 b2 = *(const float2*)(beta + col);
        gg[n][0] = g2.x; gg[n][1] = g2.y;
        bb2[n][0] = b2.x; bb2[n][1] = b2.y;
    }
    const float invs2 = 0.70710678118654752f;
#pragma unroll
    for (int m = 0; m < 2; m++)
#pragma unroll
        for (int h = 0; h < 2; h++) {
            int rr = wm * 32 + m * 16 + h * 8 + fr;
            float S = 0.f, Q = 0.f;
#pragma unroll
            for (int w = 0; w < 8; w++) { S += psum[w * 64 + rr]; Q += psq[w * 64 + rr]; }
            float mu = S * (1.f / 512.f);
            float var = Q * (1.f / 512.f) - mu * mu;
            float rstd = rsqrtf(var + LN_EPS);
            size_t orow = (row0 + rr) * 512;
#pragma unroll
            for (int n = 0; n < 8; n++) {
                int col = wn * 64 + n * 8 + fc * 2;
                float y0 = (acc[m][n][h * 2] - mu) * rstd * gg[n][0] + bb2[n][0];
                float y1 = (acc[m][n][h * 2 + 1] - mu) * rstd * gg[n][1] + bb2[n][1];
                float o0 = y0 * 0.5f * (1.f + erff(y0 * invs2));
                float o1 = y1 * 0.5f * (1.f + erff(y1 * invs2));
                *(float2*)(out + orow + col) = make_float2(o0, o1);
            }
        }
}

// ---------------- launch ----------------
extern "C" void kernel_launch(void* const* d_in, const int* in_sizes, int n_in,
                              void* d_out, int out_size) {
    const float* v     = (const float*)d_in[0];
    const float* Wd    = (const float*)d_in[1];
    const float* We    = (const float*)d_in[2];
    const float* Wl    = (const float*)d_in[3];
    const float* bl    = (const float*)d_in[4];
    const float* gamma = (const float*)d_in[5];
    const float* beta  = (const float*)d_in[6];
    float* out = (float*)d_out;

    cudaFuncSetAttribute(k1_kernel, cudaFuncAttributeMaxDynamicSharedMemorySize, K1_SMEM);
    cudaFuncSetAttribute(k2_kernel, cudaFuncAttributeMaxDynamicSharedMemorySize, K2_SMEM);

    kprep<<<1024, 256>>>(Wd, Wl);
    k1_kernel<<<NR / 64, 512, K1_SMEM>>>(v, We);
    k2_kernel<<<NR / 64, 512, K2_SMEM>>>(bl, gamma, beta, out);
}

// round 9
// speedup vs baseline: 2.2992x; 1.2064x over previous
#include <cuda_runtime.h>
#include <cuda_fp16.h>
#include <math.h>
#include <stdint.h>

#define NR 131072
#define EPS_N 1e-3f
#define LN_EPS 1e-5f

// ---- global scratch (allocation-free) ----
__device__ __half g_wd[128 * 512];
__device__ __half g_wl[512 * 512];
__device__ __half g_v2[(size_t)NR * 512];

// ---- helpers ----
__device__ __forceinline__ uint32_t smem_u32(const void* p) {
    uint32_t a;
    asm("{ .reg .u64 t; cvta.to.shared.u64 t, %1; cvt.u32.u64 %0, t; }" : "=r"(a) : "l"(p));
    return a;
}
__device__ __forceinline__ void mma_f16(float* c, uint32_t a0, uint32_t a1, uint32_t a2, uint32_t a3,
                                        uint32_t b0, uint32_t b1) {
    asm volatile("mma.sync.aligned.m16n8k16.row.col.f32.f16.f16.f32 "
                 "{%0,%1,%2,%3},{%4,%5,%6,%7},{%8,%9},{%0,%1,%2,%3};"
                 : "+f"(c[0]), "+f"(c[1]), "+f"(c[2]), "+f"(c[3])
                 : "r"(a0), "r"(a1), "r"(a2), "r"(a3), "r"(b0), "r"(b1));
}
#define LDSM4(R, A) \
    asm volatile("ldmatrix.sync.aligned.m8n8.x4.shared.b16 {%0,%1,%2,%3},[%4];" \
                 : "=r"((R)[0]), "=r"((R)[1]), "=r"((R)[2]), "=r"((R)[3]) : "r"(A))
#define CP16(dst, src) asm volatile("cp.async.ca.shared.global [%0],[%1],16;" :: "r"(dst), "l"(src) : "memory")
#define CPCOMMIT()     asm volatile("cp.async.commit_group;" ::: "memory")
#define CPWAIT0()      asm volatile("cp.async.wait_group 0;" ::: "memory")

// row stride: 64 fp16 = 128B data + 16B pad = 144B (conflict-free ldmatrix)
#define RST 144

// ---------------- prep: convert weights to fp16 ----------------
__global__ void __launch_bounds__(256) kprep(const float* __restrict__ Wd,
                                             const float* __restrict__ Wl) {
    int i = blockIdx.x * 256 + threadIdx.x;
    if (i < 128 * 512) g_wd[i] = __float2half_rn(Wd[i]);
    if (i < 512 * 512) g_wl[i] = __float2half_rn(Wl[i]);
}

// ---------------- Kernel 1: HMMA GEMM1 + scalarizer epilogue ----------------
// CTA: 64 v-rows = 192 A-rows, N=128, K chunks of 64, double-buffered.
// 512 threads, warp grid 4(M)x4(N): warp tile 48x32.
#define K1_A(b) (1536 + (b) * (192 * RST))
#define K1_B(b) (1536 + 2 * 192 * RST + (b) * (128 * RST))
#define VST 132
#define K1_SMEM (1536 + 192 * VST * 4)

__global__ void __launch_bounds__(512) k1_kernel(const float* __restrict__ v,
                                                 const float* __restrict__ We) {
    extern __shared__ char smem[];
    const uint32_t sb = smem_u32(smem);
    const int tid = threadIdx.x, wid = tid >> 5, lane = tid & 31;
    const int wm = wid & 3, wn = wid >> 2;
    const int fr = lane >> 2, fc = lane & 3;
    const int lr = lane & 7, b8 = (lane >> 3) & 1, b16 = (lane >> 4) & 1;
    const int blk = blockIdx.x;
    const float* vbase = v + (size_t)blk * 192 * 512;

    float* sWe = (float*)smem;
    for (int i = tid; i < 384; i += 512) sWe[i] = We[i];

    // cp.async B mapping: 128 rows x 8 segs(16B) = 1024 -> 2 per thread
    const int br0 = tid >> 3, bsg = tid & 7;

    const uint32_t aoff = (uint32_t)((wm * 48 + lr + b8 * 8) * RST + b16 * 16);
    const uint32_t boff = (uint32_t)((wn * 32 + lr + b8 * 8) * RST + b16 * 16);

    float acc[3][4][4];
#pragma unroll
    for (int m = 0; m < 3; m++)
#pragma unroll
        for (int n = 0; n < 4; n++)
#pragma unroll
            for (int j = 0; j < 4; j++) acc[m][n][j] = 0.f;

    float4 va[6];
    // prologue: chunk 0
#pragma unroll
    for (int t = 0; t < 2; t++) {
        int lin = tid + 512 * t;
        int r = lin >> 3, sg = lin & 7;
        CP16(sb + K1_B(0) + (uint32_t)(r * RST + sg * 16), g_wd + r * 512 + sg * 8);
    }
    CPCOMMIT();
#pragma unroll
    for (int t = 0; t < 6; t++) {
        int lin = tid + 512 * t;
        int g = lin >> 4, q = lin & 15;
        va[t] = *(const float4*)(vbase + (size_t)g * 512 + q * 4);
    }
#pragma unroll
    for (int t = 0; t < 6; t++) {
        int lin = tid + 512 * t;
        int g = lin >> 4, q = lin & 15;
        __half2 p0 = __floats2half2_rn(va[t].x, va[t].y);
        __half2 p1 = __floats2half2_rn(va[t].z, va[t].w);
        *(uint2*)(smem + K1_A(0) + g * RST + q * 8) =
            make_uint2(*(uint32_t*)&p0, *(uint32_t*)&p1);
    }
    CPWAIT0();
    __syncthreads();

    int cur = 0;
#pragma unroll
    for (int c = 0; c < 8; c++) {
        if (c < 7) {
            const int k0n = (c + 1) * 64;
#pragma unroll
            for (int t = 0; t < 2; t++) {
                int lin = tid + 512 * t;
                int r = lin >> 3, sg = lin & 7;
                CP16(sb + K1_B(cur ^ 1) + (uint32_t)(r * RST + sg * 16),
                     g_wd + r * 512 + k0n + sg * 8);
            }
            CPCOMMIT();
#pragma unroll
            for (int t = 0; t < 6; t++) {
                int lin = tid + 512 * t;
                int g = lin >> 4, q = lin & 15;
                va[t] = *(const float4*)(vbase + (size_t)g * 512 + k0n + q * 4);
            }
        }
        const uint32_t A = sb + K1_A(cur), B = sb + K1_B(cur);
#pragma unroll
        for (int ks = 0; ks < 4; ks++) {
            uint32_t a[3][4], b[2][4];
#pragma unroll
            for (int m = 0; m < 3; m++) LDSM4(a[m], A + aoff + m * 16 * RST + ks * 32);
#pragma unroll
            for (int p = 0; p < 2; p++) LDSM4(b[p], B + boff + p * 16 * RST + ks * 32);
#pragma unroll
            for (int m = 0; m < 3; m++)
#pragma unroll
                for (int n = 0; n < 4; n++)
                    mma_f16(acc[m][n], a[m][0], a[m][1], a[m][2], a[m][3],
                            b[n >> 1][n & 1], b[n >> 1][2 + (n & 1)]);
        }
        if (c < 7) {
#pragma unroll
            for (int t = 0; t < 6; t++) {
                int lin = tid + 512 * t;
                int g = lin >> 4, q = lin & 15;
                __half2 p0 = __floats2half2_rn(va[t].x, va[t].y);
                __half2 p1 = __floats2half2_rn(va[t].z, va[t].w);
                *(uint2*)(smem + K1_A(cur ^ 1) + g * RST + q * 8) =
                    make_uint2(*(uint32_t*)&p0, *(uint32_t*)&p1);
            }
            CPWAIT0();
        }
        __syncthreads();
        cur ^= 1;
    }

    // dump acc -> vred
    float* vred = (float*)(smem + 1536);
#pragma unroll
    for (int m = 0; m < 3; m++) {
        int row = wm * 48 + m * 16 + fr;
#pragma unroll
        for (int n = 0; n < 4; n++) {
            int col = wn * 32 + n * 8 + fc * 2;
            *(float2*)(vred + row * VST + col) = make_float2(acc[m][n][0], acc[m][n][1]);
            *(float2*)(vred + (row + 8) * VST + col) = make_float2(acc[m][n][2], acc[m][n][3]);
        }
    }
    __syncthreads();

    // ---- epilogue: norms, directions, projections -> v2 (fp16) ----
    float we[3][4];
#pragma unroll
    for (int e = 0; e < 3; e++)
#pragma unroll
        for (int c = 0; c < 4; c++) we[e][c] = sWe[e * 128 + lane + 32 * c];

    for (int t = 0; t < 4; t++) {
        int r = wid + 16 * t;
        size_t gr = (size_t)blk * 64 + r;
        float vr[3][4];
#pragma unroll
        for (int i = 0; i < 3; i++)
#pragma unroll
            for (int c = 0; c < 4; c++)
                vr[i][c] = vred[(r * 3 + i) * VST + lane + 32 * c];

        float d9[3][3];
#pragma unroll
        for (int i = 0; i < 3; i++)
#pragma unroll
            for (int e = 0; e < 3; e++) {
                float s = 0.f;
#pragma unroll
                for (int c = 0; c < 4; c++) s = fmaf(vr[i][c], we[e][c], s);
#pragma unroll
                for (int o = 16; o > 0; o >>= 1) s += __shfl_xor_sync(0xffffffffu, s, o);
                d9[i][e] = s;
            }
        float nd[3][3];
#pragma unroll
        for (int e = 0; e < 3; e++) {
            float dn = sqrtf(d9[0][e] * d9[0][e] + d9[1][e] * d9[1][e] + d9[2][e] * d9[2][e]);
            float inv = 1.f / (dn + EPS_N);
            nd[0][e] = d9[0][e] * inv;
            nd[1][e] = d9[1][e] * inv;
            nd[2][e] = d9[2][e] * inv;
        }
        __half* ov = g_v2 + gr * 512;
#pragma unroll
        for (int c = 0; c < 4; c++) {
            float n = sqrtf(vr[0][c] * vr[0][c] + vr[1][c] * vr[1][c] + vr[2][c] * vr[2][c]);
            float invn = 1.f / (n + EPS_N);
            int k = lane + 32 * c;
            ov[k] = __float2half_rn(n);
#pragma unroll
            for (int e = 0; e < 3; e++) {
                float p = (vr[0][c] * nd[0][e] + vr[1][c] * nd[1][e] + vr[2][c] * nd[2][e]) * invn;
                ov[128 + e * 128 + k] = __float2half_rn(p);
            }
        }
    }
}

// ---------------- Kernel 2: HMMA GEMM2 fused with LayerNorm+GELU ----------------
// CTA: 64 rows x full 512 cols. K chunks of 64, double-buffered.
// 512 threads, warp grid 2(M)x8(N): tile 32x64.
#define K2_A(b) ((b) * (64 * RST))
#define K2_B(b) (2 * 64 * RST + (b) * (512 * RST))
#define K2_PSUM (2 * 64 * RST + 2 * 512 * RST)
#define K2_PSQ (K2_PSUM + 2048)
#define K2_SMEM (K2_PSQ + 2048)

__global__ void __launch_bounds__(512) k2_kernel(const float* __restrict__ bias,
                                                 const float* __restrict__ gamma,
                                                 const float* __restrict__ beta,
                                                 float* __restrict__ out) {
    extern __shared__ char smem[];
    const uint32_t sb = smem_u32(smem);
    const int tid = threadIdx.x, wid = tid >> 5, lane = tid & 31;
    const int wm = wid & 1, wn = wid >> 1;
    const int fr = lane >> 2, fc = lane & 3;
    const int lr = lane & 7, b8 = (lane >> 3) & 1, b16 = (lane >> 4) & 1;
    const size_t row0 = (size_t)blockIdx.x * 64;

    // A: 64 rows x 8 segs = 512 -> 1 per thread
    const int ar = tid >> 3, asg = tid & 7;
    const __half* asrc = g_v2 + (row0 + ar) * 512 + asg * 8;
    const uint32_t adst = (uint32_t)(ar * RST + asg * 16);

    const uint32_t aoff = (uint32_t)((wm * 32 + lr + b8 * 8) * RST + b16 * 16);
    const uint32_t boff = (uint32_t)((wn * 64 + lr + b8 * 8) * RST + b16 * 16);

    float acc[2][8][4];
#pragma unroll
    for (int m = 0; m < 2; m++)
#pragma unroll
        for (int n = 0; n < 8; n++)
#pragma unroll
            for (int j = 0; j < 4; j++) acc[m][n][j] = 0.f;

    // prologue: chunk 0
    {
        CP16(sb + K2_A(0) + adst, asrc);
#pragma unroll
        for (int i = 0; i < 8; i++) {
            int lin = tid + 512 * i;
            int r = lin >> 3, sg = lin & 7;
            CP16(sb + K2_B(0) + (uint32_t)(r * RST + sg * 16), g_wl + (size_t)r * 512 + sg * 8);
        }
        CPCOMMIT();
        CPWAIT0();
        __syncthreads();
    }
    int cur = 0;
#pragma unroll
    for (int c = 0; c < 8; c++) {
        if (c < 7) {
            const int k0n = (c + 1) * 64;
            CP16(sb + K2_A(cur ^ 1) + adst, asrc + k0n);
#pragma unroll
            for (int i = 0; i < 8; i++) {
                int lin = tid + 512 * i;
                int r = lin >> 3, sg = lin & 7;
                CP16(sb + K2_B(cur ^ 1) + (uint32_t)(r * RST + sg * 16),
                     g_wl + (size_t)r * 512 + k0n + sg * 8);
            }
            CPCOMMIT();
        }
        const uint32_t A = sb + K2_A(cur), B = sb + K2_B(cur);
#pragma unroll
        for (int ks = 0; ks < 4; ks++) {
            uint32_t a[2][4], b[4][4];
#pragma unroll
            for (int m = 0; m < 2; m++) LDSM4(a[m], A + aoff + m * 16 * RST + ks * 32);
#pragma unroll
            for (int p = 0; p < 4; p++) LDSM4(b[p], B + boff + p * 16 * RST + ks * 32);
#pragma unroll
            for (int m = 0; m < 2; m++)
#pragma unroll
                for (int n = 0; n < 8; n++)
                    mma_f16(acc[m][n], a[m][0], a[m][1], a[m][2], a[m][3],
                            b[n >> 1][n & 1], b[n >> 1][2 + (n & 1)]);
        }
        if (c < 7) CPWAIT0();
        __syncthreads();
        cur ^= 1;
    }

    // ---- fused epilogue: bias + LayerNorm + exact GELU ----
#pragma unroll
    for (int n = 0; n < 8; n++) {
        int col = wn * 64 + n * 8 + fc * 2;
        float2 bb = *(const float2*)(bias + col);
#pragma unroll
        for (int m = 0; m < 2; m++) {
            acc[m][n][0] += bb.x; acc[m][n][1] += bb.y;
            acc[m][n][2] += bb.x; acc[m][n][3] += bb.y;
        }
    }
    float* psum = (float*)(smem + K2_PSUM);
    float* psq  = (float*)(smem + K2_PSQ);
#pragma unroll
    for (int m = 0; m < 2; m++)
#pragma unroll
        for (int h = 0; h < 2; h++) {
            float s = 0.f, q = 0.f;
#pragma unroll
            for (int n = 0; n < 8; n++) {
                float e0 = acc[m][n][h * 2], e1 = acc[m][n][h * 2 + 1];
                s += e0 + e1;
                q += e0 * e0 + e1 * e1;
            }
            s += __shfl_xor_sync(0xffffffffu, s, 1);
            s += __shfl_xor_sync(0xffffffffu, s, 2);
            q += __shfl_xor_sync(0xffffffffu, q, 1);
            q += __shfl_xor_sync(0xffffffffu, q, 2);
            int rr = wm * 32 + m * 16 + h * 8 + fr;
            if (fc == 0) { psum[wn * 64 + rr] = s; psq[wn * 64 + rr] = q; }
        }
    __syncthreads();

    float gg[8][2], bb2[8][2];
#pragma unroll
    for (int n = 0; n < 8; n++) {
        int col = wn * 64 + n * 8 + fc * 2;
        float2 g2 = *(const float2*)(gamma + col);
        float2 b2 = *(const float2*)(beta + col);
        gg[n][0] = g2.x; gg[n][1] = g2.y;
        bb2[n][0] = b2.x; bb2[n][1] = b2.y;
    }
    const float invs2 = 0.70710678118654752f;
#pragma unroll
    for (int m = 0; m < 2; m++)
#pragma unroll
        for (int h = 0; h < 2; h++) {
            int rr = wm * 32 + m * 16 + h * 8 + fr;
            float S = 0.f, Q = 0.f;
#pragma unroll
            for (int w = 0; w < 8; w++) { S += psum[w * 64 + rr]; Q += psq[w * 64 + rr]; }
            float mu = S * (1.f / 512.f);
            float var = Q * (1.f / 512.f) - mu * mu;
            float rstd = rsqrtf(var + LN_EPS);
            size_t orow = (row0 + rr) * 512;
#pragma unroll
            for (int n = 0; n < 8; n++) {
                int col = wn * 64 + n * 8 + fc * 2;
                float y0 = (acc[m][n][h * 2] - mu) * rstd * gg[n][0] + bb2[n][0];
                float y1 = (acc[m][n][h * 2 + 1] - mu) * rstd * gg[n][1] + bb2[n][1];
                float o0 = y0 * 0.5f * (1.f + erff(y0 * invs2));
                float o1 = y1 * 0.5f * (1.f + erff(y1 * invs2));
                *(float2*)(out + orow + col) = make_float2(o0, o1);
            }
        }
}

// ---------------- launch ----------------
extern "C" void kernel_launch(void* const* d_in, const int* in_sizes, int n_in,
                              void* d_out, int out_size) {
    const float* v     = (const float*)d_in[0];
    const float* Wd    = (const float*)d_in[1];
    const float* We    = (const float*)d_in[2];
    const float* Wl    = (const float*)d_in[3];
    const float* bl    = (const float*)d_in[4];
    const float* gamma = (const float*)d_in[5];
    const float* beta  = (const float*)d_in[6];
    float* out = (float*)d_out;

    cudaFuncSetAttribute(k1_kernel, cudaFuncAttributeMaxDynamicSharedMemorySize, K1_SMEM);
    cudaFuncSetAttribute(k2_kernel, cudaFuncAttributeMaxDynamicSharedMemorySize, K2_SMEM);

    kprep<<<1024, 256>>>(Wd, Wl);
    k1_kernel<<<NR / 64, 512, K1_SMEM>>>(v, We);
    k2_kernel<<<NR / 64, 512, K2_SMEM>>>(bl, gamma, beta, out);
}

// round 10
// speedup vs baseline: 2.3888x; 1.0390x over previous
#include <cuda_runtime.h>
#include <cuda_fp16.h>
#include <math.h>
#include <stdint.h>

#define NR 131072
#define EPS_N 1e-3f
#define LN_EPS 1e-5f

// ---- global scratch (allocation-free) ----
__device__ __half g_wd[128 * 512];
__device__ __half g_wl[512 * 512];
__device__ __half g_v2[(size_t)NR * 512];

// ---- helpers ----
__device__ __forceinline__ uint32_t smem_u32(const void* p) {
    uint32_t a;
    asm("{ .reg .u64 t; cvta.to.shared.u64 t, %1; cvt.u32.u64 %0, t; }" : "=r"(a) : "l"(p));
    return a;
}
__device__ __forceinline__ void mma_f16(float* c, uint32_t a0, uint32_t a1, uint32_t a2, uint32_t a3,
                                        uint32_t b0, uint32_t b1) {
    asm volatile("mma.sync.aligned.m16n8k16.row.col.f32.f16.f16.f32 "
                 "{%0,%1,%2,%3},{%4,%5,%6,%7},{%8,%9},{%0,%1,%2,%3};"
                 : "+f"(c[0]), "+f"(c[1]), "+f"(c[2]), "+f"(c[3])
                 : "r"(a0), "r"(a1), "r"(a2), "r"(a3), "r"(b0), "r"(b1));
}
#define LDSM4(R, A) \
    asm volatile("ldmatrix.sync.aligned.m8n8.x4.shared.b16 {%0,%1,%2,%3},[%4];" \
                 : "=r"((R)[0]), "=r"((R)[1]), "=r"((R)[2]), "=r"((R)[3]) : "r"(A))
#define CP16(dst, src) asm volatile("cp.async.ca.shared.global [%0],[%1],16;" :: "r"(dst), "l"(src) : "memory")
#define CPCOMMIT()     asm volatile("cp.async.commit_group;" ::: "memory")
#define CPWAIT0()      asm volatile("cp.async.wait_group 0;" ::: "memory")

// row stride: 64 fp16 = 128B data + 16B pad = 144B (conflict-free ldmatrix)
#define RST 144

// ---------------- prep: convert weights to fp16 ----------------
__global__ void __launch_bounds__(256) kprep(const float* __restrict__ Wd,
                                             const float* __restrict__ Wl) {
    int i = blockIdx.x * 256 + threadIdx.x;
    if (i < 128 * 512) g_wd[i] = __float2half_rn(Wd[i]);
    if (i < 512 * 512) g_wl[i] = __float2half_rn(Wl[i]);
}

// ---------------- Kernel 1: HMMA GEMM1 + scalarizer epilogue ----------------
// CTA: 32 v-rows = 96 A-rows, N=128, K chunks of 64, double-buffered.
// 256 threads, warp grid 2(M)x4(N): warp tile 48x32. 2 CTAs/SM target.
#define K1_A(b) (1536 + (b) * (96 * RST))
#define K1_B(b) (1536 + 2 * 96 * RST + (b) * (128 * RST))
#define VST 132
#define K1_SMEM (1536 + 2 * 96 * RST + 2 * 128 * RST)

__global__ void __launch_bounds__(256) k1_kernel(const float* __restrict__ v,
                                                 const float* __restrict__ We) {
    extern __shared__ char smem[];
    const uint32_t sb = smem_u32(smem);
    const int tid = threadIdx.x, wid = tid >> 5, lane = tid & 31;
    const int wm = wid & 1, wn = wid >> 1;          // 2(M) x 4(N)
    const int fr = lane >> 2, fc = lane & 3;
    const int lr = lane & 7, b8 = (lane >> 3) & 1, b16 = (lane >> 4) & 1;
    const int blk = blockIdx.x;
    const float* vbase = v + (size_t)blk * 96 * 512;

    float* sWe = (float*)smem;
    for (int i = tid; i < 384; i += 256) sWe[i] = We[i];

    const uint32_t aoff = (uint32_t)((wm * 48 + lr + b8 * 8) * RST + b16 * 16);
    const uint32_t boff = (uint32_t)((wn * 32 + lr + b8 * 8) * RST + b16 * 16);

    float acc[3][4][4];
#pragma unroll
    for (int m = 0; m < 3; m++)
#pragma unroll
        for (int n = 0; n < 4; n++)
#pragma unroll
            for (int j = 0; j < 4; j++) acc[m][n][j] = 0.f;

    float4 va[6];
    // prologue: chunk 0
#pragma unroll
    for (int t = 0; t < 4; t++) {
        int lin = tid + 256 * t;
        int r = lin >> 3, sg = lin & 7;
        CP16(sb + K1_B(0) + (uint32_t)(r * RST + sg * 16), g_wd + r * 512 + sg * 8);
    }
    CPCOMMIT();
#pragma unroll
    for (int t = 0; t < 6; t++) {
        int lin = tid + 256 * t;
        int g = lin >> 4, q = lin & 15;
        va[t] = *(const float4*)(vbase + (size_t)g * 512 + q * 4);
    }
#pragma unroll
    for (int t = 0; t < 6; t++) {
        int lin = tid + 256 * t;
        int g = lin >> 4, q = lin & 15;
        __half2 p0 = __floats2half2_rn(va[t].x, va[t].y);
        __half2 p1 = __floats2half2_rn(va[t].z, va[t].w);
        *(uint2*)(smem + K1_A(0) + g * RST + q * 8) =
            make_uint2(*(uint32_t*)&p0, *(uint32_t*)&p1);
    }
    CPWAIT0();
    __syncthreads();

    int cur = 0;
#pragma unroll
    for (int c = 0; c < 8; c++) {
        if (c < 7) {
            const int k0n = (c + 1) * 64;
#pragma unroll
            for (int t = 0; t < 4; t++) {
                int lin = tid + 256 * t;
                int r = lin >> 3, sg = lin & 7;
                CP16(sb + K1_B(cur ^ 1) + (uint32_t)(r * RST + sg * 16),
                     g_wd + r * 512 + k0n + sg * 8);
            }
            CPCOMMIT();
#pragma unroll
            for (int t = 0; t < 6; t++) {
                int lin = tid + 256 * t;
                int g = lin >> 4, q = lin & 15;
                va[t] = *(const float4*)(vbase + (size_t)g * 512 + k0n + q * 4);
            }
        }
        const uint32_t A = sb + K1_A(cur), B = sb + K1_B(cur);
#pragma unroll
        for (int ks = 0; ks < 4; ks++) {
            uint32_t a[3][4], b[2][4];
#pragma unroll
            for (int m = 0; m < 3; m++) LDSM4(a[m], A + aoff + m * 16 * RST + ks * 32);
#pragma unroll
            for (int p = 0; p < 2; p++) LDSM4(b[p], B + boff + p * 16 * RST + ks * 32);
#pragma unroll
            for (int m = 0; m < 3; m++)
#pragma unroll
                for (int n = 0; n < 4; n++)
                    mma_f16(acc[m][n], a[m][0], a[m][1], a[m][2], a[m][3],
                            b[n >> 1][n & 1], b[n >> 1][2 + (n & 1)]);
        }
        if (c < 7) {
#pragma unroll
            for (int t = 0; t < 6; t++) {
                int lin = tid + 256 * t;
                int g = lin >> 4, q = lin & 15;
                __half2 p0 = __floats2half2_rn(va[t].x, va[t].y);
                __half2 p1 = __floats2half2_rn(va[t].z, va[t].w);
                *(uint2*)(smem + K1_A(cur ^ 1) + g * RST + q * 8) =
                    make_uint2(*(uint32_t*)&p0, *(uint32_t*)&p1);
            }
            CPWAIT0();
        }
        __syncthreads();
        cur ^= 1;
    }

    // dump acc -> vred (union over operand buffers; safe after final sync)
    float* vred = (float*)(smem + 1536);
#pragma unroll
    for (int m = 0; m < 3; m++) {
        int row = wm * 48 + m * 16 + fr;
#pragma unroll
        for (int n = 0; n < 4; n++) {
            int col = wn * 32 + n * 8 + fc * 2;
            *(float2*)(vred + row * VST + col) = make_float2(acc[m][n][0], acc[m][n][1]);
            *(float2*)(vred + (row + 8) * VST + col) = make_float2(acc[m][n][2], acc[m][n][3]);
        }
    }
    __syncthreads();

    // ---- epilogue: norms, directions, projections -> v2 (fp16) ----
    float we[3][4];
#pragma unroll
    for (int e = 0; e < 3; e++)
#pragma unroll
        for (int c = 0; c < 4; c++) we[e][c] = sWe[e * 128 + lane + 32 * c];

    for (int t = 0; t < 4; t++) {
        int r = wid + 8 * t;                 // v-row within CTA (0..31)
        size_t gr = (size_t)blk * 32 + r;
        float vr[3][4];
#pragma unroll
        for (int i = 0; i < 3; i++)
#pragma unroll
            for (int c = 0; c < 4; c++)
                vr[i][c] = vred[(r * 3 + i) * VST + lane + 32 * c];

        float d9[3][3];
#pragma unroll
        for (int i = 0; i < 3; i++)
#pragma unroll
            for (int e = 0; e < 3; e++) {
                float s = 0.f;
#pragma unroll
                for (int c = 0; c < 4; c++) s = fmaf(vr[i][c], we[e][c], s);
#pragma unroll
                for (int o = 16; o > 0; o >>= 1) s += __shfl_xor_sync(0xffffffffu, s, o);
                d9[i][e] = s;
            }
        float nd[3][3];
#pragma unroll
        for (int e = 0; e < 3; e++) {
            float dn = sqrtf(d9[0][e] * d9[0][e] + d9[1][e] * d9[1][e] + d9[2][e] * d9[2][e]);
            float inv = 1.f / (dn + EPS_N);
            nd[0][e] = d9[0][e] * inv;
            nd[1][e] = d9[1][e] * inv;
            nd[2][e] = d9[2][e] * inv;
        }
        __half* ov = g_v2 + gr * 512;
#pragma unroll
        for (int c = 0; c < 4; c++) {
            float n = sqrtf(vr[0][c] * vr[0][c] + vr[1][c] * vr[1][c] + vr[2][c] * vr[2][c]);
            float invn = 1.f / (n + EPS_N);
            int k = lane + 32 * c;
            ov[k] = __float2half_rn(n);
#pragma unroll
            for (int e = 0; e < 3; e++) {
                float p = (vr[0][c] * nd[0][e] + vr[1][c] * nd[1][e] + vr[2][c] * nd[2][e]) * invn;
                ov[128 + e * 128 + k] = __float2half_rn(p);
            }
        }
    }
}

// ---------------- Kernel 2: HMMA GEMM2 fused with LayerNorm+GELU ----------------
// CTA: 64 rows x full 512 cols. K chunks of 64, double-buffered.
// 512 threads, warp grid 2(M)x8(N): tile 32x64.
#define K2_A(b) ((b) * (64 * RST))
#define K2_B(b) (2 * 64 * RST + (b) * (512 * RST))
#define K2_PSUM (2 * 64 * RST + 2 * 512 * RST)
#define K2_PSQ (K2_PSUM + 2048)
#define K2_SMEM (K2_PSQ + 2048)

__global__ void __launch_bounds__(512) k2_kernel(const float* __restrict__ bias,
                                                 const float* __restrict__ gamma,
                                                 const float* __restrict__ beta,
                                                 float* __restrict__ out) {
    extern __shared__ char smem[];
    const uint32_t sb = smem_u32(smem);
    const int tid = threadIdx.x, wid = tid >> 5, lane = tid & 31;
    const int wm = wid & 1, wn = wid >> 1;
    const int fr = lane >> 2, fc = lane & 3;
    const int lr = lane & 7, b8 = (lane >> 3) & 1, b16 = (lane >> 4) & 1;
    const size_t row0 = (size_t)blockIdx.x * 64;

    // A: 64 rows x 8 segs = 512 -> 1 per thread
    const int ar = tid >> 3, asg = tid & 7;
    const __half* asrc = g_v2 + (row0 + ar) * 512 + asg * 8;
    const uint32_t adst = (uint32_t)(ar * RST + asg * 16);

    const uint32_t aoff = (uint32_t)((wm * 32 + lr + b8 * 8) * RST + b16 * 16);
    const uint32_t boff = (uint32_t)((wn * 64 + lr + b8 * 8) * RST + b16 * 16);

    float acc[2][8][4];
#pragma unroll
    for (int m = 0; m < 2; m++)
#pragma unroll
        for (int n = 0; n < 8; n++)
#pragma unroll
            for (int j = 0; j < 4; j++) acc[m][n][j] = 0.f;

    // prologue: chunk 0
    {
        CP16(sb + K2_A(0) + adst, asrc);
#pragma unroll
        for (int i = 0; i < 8; i++) {
            int lin = tid + 512 * i;
            int r = lin >> 3, sg = lin & 7;
            CP16(sb + K2_B(0) + (uint32_t)(r * RST + sg * 16), g_wl + (size_t)r * 512 + sg * 8);
        }
        CPCOMMIT();
        CPWAIT0();
        __syncthreads();
    }
    int cur = 0;
#pragma unroll
    for (int c = 0; c < 8; c++) {
        if (c < 7) {
            const int k0n = (c + 1) * 64;
            CP16(sb + K2_A(cur ^ 1) + adst, asrc + k0n);
#pragma unroll
            for (int i = 0; i < 8; i++) {
                int lin = tid + 512 * i;
                int r = lin >> 3, sg = lin & 7;
                CP16(sb + K2_B(cur ^ 1) + (uint32_t)(r * RST + sg * 16),
                     g_wl + (size_t)r * 512 + k0n + sg * 8);
            }
            CPCOMMIT();
        }
        const uint32_t A = sb + K2_A(cur), B = sb + K2_B(cur);
#pragma unroll
        for (int ks = 0; ks < 4; ks++) {
            uint32_t a[2][4], b[4][4];
#pragma unroll
            for (int m = 0; m < 2; m++) LDSM4(a[m], A + aoff + m * 16 * RST + ks * 32);
#pragma unroll
            for (int p = 0; p < 4; p++) LDSM4(b[p], B + boff + p * 16 * RST + ks * 32);
#pragma unroll
            for (int m = 0; m < 2; m++)
#pragma unroll
                for (int n = 0; n < 8; n++)
                    mma_f16(acc[m][n], a[m][0], a[m][1], a[m][2], a[m][3],
                            b[n >> 1][n & 1], b[n >> 1][2 + (n & 1)]);
        }
        if (c < 7) CPWAIT0();
        __syncthreads();
        cur ^= 1;
    }

    // ---- fused epilogue: bias + LayerNorm + exact GELU ----
#pragma unroll
    for (int n = 0; n < 8; n++) {
        int col = wn * 64 + n * 8 + fc * 2;
        float2 bb = *(const float2*)(bias + col);
#pragma unroll
        for (int m = 0; m < 2; m++) {
            acc[m][n][0] += bb.x; acc[m][n][1] += bb.y;
            acc[m][n][2] += bb.x; acc[m][n][3] += bb.y;
        }
    }
    float* psum = (float*)(smem + K2_PSUM);
    float* psq  = (float*)(smem + K2_PSQ);
#pragma unroll
    for (int m = 0; m < 2; m++)
#pragma unroll
        for (int h = 0; h < 2; h++) {
            float s = 0.f, q = 0.f;
#pragma unroll
            for (int n = 0; n < 8; n++) {
                float e0 = acc[m][n][h * 2], e1 = acc[m][n][h * 2 + 1];
                s += e0 + e1;
                q += e0 * e0 + e1 * e1;
            }
            s += __shfl_xor_sync(0xffffffffu, s, 1);
            s += __shfl_xor_sync(0xffffffffu, s, 2);
            q += __shfl_xor_sync(0xffffffffu, q, 1);
            q += __shfl_xor_sync(0xffffffffu, q, 2);
            int rr = wm * 32 + m * 16 + h * 8 + fr;
            if (fc == 0) { psum[wn * 64 + rr] = s; psq[wn * 64 + rr] = q; }
        }
    __syncthreads();

    float gg[8][2], bb2[8][2];
#pragma unroll
    for (int n = 0; n < 8; n++) {
        int col = wn * 64 + n * 8 + fc * 2;
        float2 g2 = *(const float2*)(gamma + col);
        float2 b2 = *(const float2*)(beta + col);
        gg[n][0] = g2.x; gg[n][1] = g2.y;
        bb2[n][0] = b2.x; bb2[n][1] = b2.y;
    }
    const float invs2 = 0.70710678118654752f;
#pragma unroll
    for (int m = 0; m < 2; m++)
#pragma unroll
        for (int h = 0; h < 2; h++) {
            int rr = wm * 32 + m * 16 + h * 8 + fr;
            float S = 0.f, Q = 0.f;
#pragma unroll
            for (int w = 0; w < 8; w++) { S += psum[w * 64 + rr]; Q += psq[w * 64 + rr]; }
            float mu = S * (1.f / 512.f);
            float var = Q * (1.f / 512.f) - mu * mu;
            float rstd = rsqrtf(var + LN_EPS);
            size_t orow = (row0 + rr) * 512;
#pragma unroll
            for (int n = 0; n < 8; n++) {
                int col = wn * 64 + n * 8 + fc * 2;
                float y0 = (acc[m][n][h * 2] - mu) * rstd * gg[n][0] + bb2[n][0];
                float y1 = (acc[m][n][h * 2 + 1] - mu) * rstd * gg[n][1] + bb2[n][1];
                float o0 = y0 * 0.5f * (1.f + erff(y0 * invs2));
                float o1 = y1 * 0.5f * (1.f + erff(y1 * invs2));
                *(float2*)(out + orow + col) = make_float2(o0, o1);
            }
        }
}

// ---------------- launch ----------------
extern "C" void kernel_launch(void* const* d_in, const int* in_sizes, int n_in,
                              void* d_out, int out_size) {
    const float* v     = (const float*)d_in[0];
    const float* Wd    = (const float*)d_in[1];
    const float* We    = (const float*)d_in[2];
    const float* Wl    = (const float*)d_in[3];
    const float* bl    = (const float*)d_in[4];
    const float* gamma = (const float*)d_in[5];
    const float* beta  = (const float*)d_in[6];
    float* out = (float*)d_out;

    cudaFuncSetAttribute(k1_kernel, cudaFuncAttributeMaxDynamicSharedMemorySize, K1_SMEM);
    cudaFuncSetAttribute(k2_kernel, cudaFuncAttributeMaxDynamicSharedMemorySize, K2_SMEM);

    kprep<<<1024, 256>>>(Wd, Wl);
    k1_kernel<<<NR / 32, 256, K1_SMEM>>>(v, We);
    k2_kernel<<<NR / 64, 512, K2_SMEM>>>(bl, gamma, beta, out);
}